// round 5
// baseline (speedup 1.0000x reference)
#include <cuda_runtime.h>
#include <cstdint>
#include <cstddef>

#define N_MAX 50000
#define E_MAX 500000

// ---------------- scratch ----------------
__device__ float g_PQ[(size_t)N_MAX * 256];
__device__ float g_edge_m[(size_t)E_MAX * 128];
__device__ float g_B1[256 * 128];
__device__ float g_B3[128 * 128];
__device__ float g_edge_e[E_MAX];
__device__ float g_rel_att[E_MAX];
__device__ float g_arow[N_MAX];
__device__ float g_erow[N_MAX];
__device__ float g_ecol[N_MAX];
__device__ float g_new_rank[N_MAX];

// ---------------- init ----------------
__global__ void k_init(float* __restrict__ out, int N) {
    int i = blockIdx.x * blockDim.x + threadIdx.x;
    int total = N * 128;
    if (i < total) out[i] = 0.0f;
    if (i < N) { g_arow[i] = 0.0f; g_erow[i] = 0.0f; g_ecol[i] = 0.0f; }
}

// ---------------- weight extraction ----------------
__global__ void k_prep(const float* __restrict__ a) {
    int i = blockIdx.x * blockDim.x + threadIdx.x;
    if (i < 256 * 128) {
        int o = i >> 7, k = i & 127;
        g_B1[i] = (o < 128) ? a[o * 384 + k] : a[(o - 128) * 384 + 128 + k];
    }
    if (i < 128 * 128) {
        int o = i >> 7, k = i & 127;
        g_B3[i] = a[o * 384 + 256 + k];
    }
}

// packed f32x2 FMA (not emitted by ptxas from C++ — PTX only)
__device__ __forceinline__ void fma_x2(unsigned long long& d,
                                       unsigned long long a,
                                       unsigned long long b,
                                       unsigned long long c) {
    asm("fma.rn.f32x2 %0, %1, %2, %3;" : "=l"(d) : "l"(a), "l"(b), "l"(c));
}
__device__ __forceinline__ unsigned long long pack2(float lo, float hi) {
    unsigned long long r;
    asm("mov.b64 %0, {%1, %2};" : "=l"(r) : "f"(lo), "f"(hi));
    return r;
}

// ---------------- SGEMM: C[m][n] = sum_k A[m][k]*B[n][k], K=128 ----------------
__global__ __launch_bounds__(256) void k_sgemm(
    const float* __restrict__ A0, const float* __restrict__ A1, int splitM,
    int M, int mode)
{
    __shared__ __align__(16) float As[16][128];
    __shared__ __align__(16) float Bs[16][128];

    const float* __restrict__ B = (mode == 0) ? g_B1 : g_B3;
    float* __restrict__ C = (mode == 0) ? g_PQ : g_edge_m;
    const int ldc = (mode == 0) ? 256 : 128;

    int t  = threadIdx.x;
    int m0 = blockIdx.x * 128;
    int n0 = blockIdx.y * 128;
    int tx = t & 15, ty = t >> 4;

    // acc2[i][jp] = packed pair (acc[i][2jp], acc[i][2jp+1])
    unsigned long long acc2[8][4];
#pragma unroll
    for (int i = 0; i < 8; i++)
#pragma unroll
        for (int jp = 0; jp < 4; jp++) acc2[i][jp] = 0ULL;

    int lr = t >> 2;
    int lc = (t & 3) * 4;

    for (int kc = 0; kc < 128; kc += 16) {
#pragma unroll
        for (int h = 0; h < 2; ++h) {
            int m = m0 + lr + h * 64;
            float4 v = make_float4(0.f, 0.f, 0.f, 0.f);
            if (m < M) {
                const float* arow = (m < splitM) ? (A0 + (size_t)m * 128)
                                                 : (A1 + (size_t)(m - splitM) * 128);
                v = *reinterpret_cast<const float4*>(arow + kc + lc);
            }
            As[lc + 0][lr + h * 64] = v.x;
            As[lc + 1][lr + h * 64] = v.y;
            As[lc + 2][lr + h * 64] = v.z;
            As[lc + 3][lr + h * 64] = v.w;
        }
#pragma unroll
        for (int h = 0; h < 2; ++h) {
            int n = n0 + lr + h * 64;
            float4 v = *reinterpret_cast<const float4*>(B + (size_t)n * 128 + kc + lc);
            Bs[lc + 0][lr + h * 64] = v.x;
            Bs[lc + 1][lr + h * 64] = v.y;
            Bs[lc + 2][lr + h * 64] = v.z;
            Bs[lc + 3][lr + h * 64] = v.w;
        }
        __syncthreads();

#pragma unroll
        for (int kk = 0; kk < 16; ++kk) {
            float4 a0v = *reinterpret_cast<const float4*>(&As[kk][ty * 8]);
            float4 a1v = *reinterpret_cast<const float4*>(&As[kk][ty * 8 + 4]);
            float4 b0v = *reinterpret_cast<const float4*>(&Bs[kk][tx * 8]);
            float4 b1v = *reinterpret_cast<const float4*>(&Bs[kk][tx * 8 + 4]);

            unsigned long long ad[8];
            ad[0] = pack2(a0v.x, a0v.x); ad[1] = pack2(a0v.y, a0v.y);
            ad[2] = pack2(a0v.z, a0v.z); ad[3] = pack2(a0v.w, a0v.w);
            ad[4] = pack2(a1v.x, a1v.x); ad[5] = pack2(a1v.y, a1v.y);
            ad[6] = pack2(a1v.z, a1v.z); ad[7] = pack2(a1v.w, a1v.w);

            unsigned long long bp[4];
            bp[0] = pack2(b0v.x, b0v.y); bp[1] = pack2(b0v.z, b0v.w);
            bp[2] = pack2(b1v.x, b1v.y); bp[3] = pack2(b1v.z, b1v.w);

#pragma unroll
            for (int i = 0; i < 8; i++)
#pragma unroll
                for (int jp = 0; jp < 4; jp++)
                    fma_x2(acc2[i][jp], ad[i], bp[jp], acc2[i][jp]);
        }
        __syncthreads();
    }

#pragma unroll
    for (int i = 0; i < 8; i++) {
        int m = m0 + ty * 8 + i;
        if (m >= M) continue;
        float* crow = C + (size_t)m * ldc + n0 + tx * 8;
        float2 p0 = *reinterpret_cast<float2*>(&acc2[i][0]);
        float2 p1 = *reinterpret_cast<float2*>(&acc2[i][1]);
        float2 p2 = *reinterpret_cast<float2*>(&acc2[i][2]);
        float2 p3 = *reinterpret_cast<float2*>(&acc2[i][3]);
        *reinterpret_cast<float4*>(crow)     = make_float4(p0.x, p0.y, p1.x, p1.y);
        *reinterpret_cast<float4*>(crow + 4) = make_float4(p2.x, p2.y, p3.x, p3.y);
    }
}

// ---------------- helpers (edge indices are int32) ----------------
__device__ __forceinline__ void edge_src_dst(
    const int* __restrict__ edge, const int* __restrict__ nhop,
    int e, int E1, int E2, int& src, int& dst)
{
    if (e < E1) { src = edge[e]; dst = edge[E1 + e]; }
    else        { int e2 = e - E1; src = nhop[e2]; dst = nhop[E2 + e2]; }
}

__device__ __forceinline__ float lrelu(float x) { return (x > 0.0f) ? x : 0.2f * x; }

// ---------------- per-edge (warp per edge, float4 lanes) ----------------
__global__ __launch_bounds__(128) void k_edge(
    const int* __restrict__ edge, const int* __restrict__ nhop,
    const float* __restrict__ a2, int E1, int E2, int E)
{
    int e = blockIdx.x * 4 + (threadIdx.x >> 5);
    if (e >= E) return;
    int lane = threadIdx.x & 31;
    int src, dst;
    edge_src_dst(edge, nhop, e, E1, E2, src, dst);

    float4 r = *reinterpret_cast<const float4*>(&g_edge_m[(size_t)e * 128 + lane * 4]);
    float4 p = *reinterpret_cast<const float4*>(&g_PQ[(size_t)src * 256 + lane * 4]);
    float4 q = *reinterpret_cast<const float4*>(&g_PQ[(size_t)dst * 256 + 128 + lane * 4]);
    float4 av = reinterpret_cast<const float4*>(a2)[lane];

    float4 m;
    m.x = lrelu(r.x + p.x + q.x);
    m.y = lrelu(r.y + p.y + q.y);
    m.z = lrelu(r.z + p.z + q.z);
    m.w = lrelu(r.w + p.w + q.w);
    *reinterpret_cast<float4*>(&g_edge_m[(size_t)e * 128 + lane * 4]) = m;

    float s = m.x * av.x + m.y * av.y + m.z * av.z + m.w * av.w;
#pragma unroll
    for (int off = 16; off > 0; off >>= 1)
        s += __shfl_xor_sync(0xffffffffu, s, off);

    if (lane == 0) {
        float ee = expf(-lrelu(s));
        g_edge_e[e] = ee;
        atomicAdd(&g_arow[dst], ee);
    }
}

// ---------------- rel_att + e_rowsum ----------------
__global__ void k_rel(const int* __restrict__ edge, const int* __restrict__ nhop,
                      int E1, int E2, int E)
{
    int e = blockIdx.x * blockDim.x + threadIdx.x;
    if (e >= E) return;
    int src, dst;
    edge_src_dst(edge, nhop, e, E1, E2, src, dst);
    float as = g_arow[dst];
    if (as == 0.0f) as = 1e-12f;
    float r = g_edge_e[e] / as;
    g_rel_att[e] = r;
    atomicAdd(&g_erow[src], r);
}

// ---------------- val + e_colsum ----------------
__global__ void k_val(const int* __restrict__ edge, const int* __restrict__ nhop,
                      const float* __restrict__ entity_rank, int E1, int E2, int E)
{
    int e = blockIdx.x * blockDim.x + threadIdx.x;
    if (e >= E) return;
    int src, dst;
    edge_src_dst(edge, nhop, e, E1, E2, src, dst);
    float es = g_erow[src];
    if (es == 0.0f) es = 1e-12f;
    float v = g_rel_att[e] * entity_rank[src] / es;
    atomicAdd(&g_ecol[dst], v);
}

// ---------------- new_rank ----------------
__global__ void k_rank(float* __restrict__ out, int N, int out_size) {
    int n = blockIdx.x * blockDim.x + threadIdx.x;
    if (n >= N) return;
    float nr = 0.15f + 0.85f * g_ecol[n];
    g_new_rank[n] = nr;
    if (out_size >= N * 128 + N) out[(size_t)N * 128 + n] = nr;
}

// ---------------- scatter with vector RED ----------------
__global__ __launch_bounds__(128) void k_scatter(
    const int* __restrict__ edge, const int* __restrict__ nhop,
    float* __restrict__ out, int E1, int E2, int E)
{
    int e = blockIdx.x * 4 + (threadIdx.x >> 5);
    if (e >= E) return;
    int lane = threadIdx.x & 31;
    int src, dst;
    edge_src_dst(edge, nhop, e, E1, E2, src, dst);
    float w = g_rel_att[e] * g_new_rank[src];
    float4 v = *reinterpret_cast<const float4*>(&g_edge_m[(size_t)e * 128 + lane * 4]);
    float* p = out + (size_t)dst * 128 + lane * 4;
    asm volatile("red.global.add.v4.f32 [%0], {%1, %2, %3, %4};"
                 :: "l"(p), "f"(w * v.x), "f"(w * v.y), "f"(w * v.z), "f"(w * v.w)
                 : "memory");
}

// ---------------- ELU ----------------
__global__ void k_elu(float* __restrict__ out, int total) {
    int i = blockIdx.x * blockDim.x + threadIdx.x;
    if (i >= total) return;
    float x = out[i];
    out[i] = (x > 0.0f) ? x : expm1f(x);
}

// ---------------- launch ----------------
extern "C" void kernel_launch(void* const* d_in, const int* in_sizes, int n_in,
                              void* d_out, int out_size) {
    const float* input       = (const float*)d_in[0];
    const int*   edge        = (const int*)d_in[1];
    const float* edge_embed  = (const float*)d_in[2];
    const int*   edge_nhop   = (const int*)d_in[3];
    const float* embed_nhop  = (const float*)d_in[4];
    const float* entity_rank = (const float*)d_in[5];
    const float* a           = (const float*)d_in[6];
    const float* a2          = (const float*)d_in[7];
    float* out = (float*)d_out;

    int N  = in_sizes[0] / 128;
    int E1 = in_sizes[1] / 2;
    int E2 = in_sizes[3] / 2;
    int E  = E1 + E2;

    k_init<<<(N * 128 + 255) / 256, 256>>>(out, N);
    k_prep<<<(256 * 128 + 255) / 256, 256>>>(a);

    dim3 g_pq((N + 127) / 128, 2);
    k_sgemm<<<g_pq, 256>>>(input, input, N, N, 0);

    dim3 g_r((E + 127) / 128, 1);
    k_sgemm<<<g_r, 256>>>(edge_embed, embed_nhop, E1, E, 1);

    k_edge<<<(E + 3) / 4, 128>>>(edge, edge_nhop, a2, E1, E2, E);
    k_rel<<<(E + 255) / 256, 256>>>(edge, edge_nhop, E1, E2, E);
    k_val<<<(E + 255) / 256, 256>>>(edge, edge_nhop, entity_rank, E1, E2, E);
    k_rank<<<(N + 255) / 256, 256>>>(out, N, out_size);
    k_scatter<<<(E + 3) / 4, 128>>>(edge, edge_nhop, out, E1, E2, E);
    k_elu<<<(N * 128 + 255) / 256, 256>>>(out, N * 128);
}

// round 7
// speedup vs baseline: 1.5831x; 1.5831x over previous
#include <cuda_runtime.h>
#include <cstdint>
#include <cstddef>

#define N_MAX 50000
#define E_MAX 500000

// ---------------- scratch ----------------
__device__ float g_PQ[(size_t)N_MAX * 256];
__device__ float g_edge_m[(size_t)E_MAX * 128];
__device__ float g_B1[256 * 128];
__device__ float g_B3[128 * 128];
__device__ float g_edge_e[E_MAX];
__device__ float g_rel_att[E_MAX];
__device__ float g_arow[N_MAX];
__device__ float g_erow[N_MAX];
__device__ float g_ecol[N_MAX];
__device__ float g_new_rank[N_MAX];

// ---------------- init ----------------
__global__ void k_init(float* __restrict__ out, int N) {
    int i = blockIdx.x * blockDim.x + threadIdx.x;
    int total = N * 128;
    if (i < total) out[i] = 0.0f;
    if (i < N) { g_arow[i] = 0.0f; g_erow[i] = 0.0f; g_ecol[i] = 0.0f; }
}

// ---------------- weight extraction ----------------
__global__ void k_prep(const float* __restrict__ a) {
    int i = blockIdx.x * blockDim.x + threadIdx.x;
    if (i < 256 * 128) {
        int o = i >> 7, k = i & 127;
        g_B1[i] = (o < 128) ? a[o * 384 + k] : a[(o - 128) * 384 + 128 + k];
    }
    if (i < 128 * 128) {
        int o = i >> 7, k = i & 127;
        g_B3[i] = a[o * 384 + 256 + k];
    }
}

__device__ __forceinline__ float lrelu(float x) { return (x > 0.0f) ? x : 0.2f * x; }

// edge indices are int32 (JAX downcasts int64 without x64 enabled)
__device__ __forceinline__ void edge_src_dst(
    const int* __restrict__ edge, const int* __restrict__ nhop,
    int e, int E1, int E2, int& src, int& dst)
{
    if (e < E1) { src = edge[e]; dst = edge[E1 + e]; }
    else        { int e2 = e - E1; src = nhop[e2]; dst = nhop[E2 + e2]; }
}

// ---------------- SGEMM: C[m][n] = sum_k A[m][k]*B[n][k], K=128 ----------------
// mode 0: B=g_B1 (256 rows), C=g_PQ, ldc=256, plain store epilogue
// mode 1: B=g_B3 (128 rows), C=g_edge_m, ldc=128, FUSED edge epilogue:
//         m = lrelu(R + P[src] + Q[dst]); store m; edge_e = exp(-lrelu(m . a2));
//         atomic a_rowsum[dst].
__global__ __launch_bounds__(256, 2) void k_sgemm(
    const float* __restrict__ A0, const float* __restrict__ A1, int splitM,
    int M, int mode,
    const int* __restrict__ edge, const int* __restrict__ nhop,
    const float* __restrict__ a2, int E1, int E2)
{
    __shared__ __align__(16) float As[16][128];
    __shared__ __align__(16) float Bs[16][128];

    const float* __restrict__ B = (mode == 0) ? g_B1 : g_B3;
    float* __restrict__ C = (mode == 0) ? g_PQ : g_edge_m;
    const int ldc = (mode == 0) ? 256 : 128;

    int t  = threadIdx.x;
    int m0 = blockIdx.x * 128;
    int n0 = blockIdx.y * 128;
    int tx = t & 15, ty = t >> 4;

    float acc[8][8];
#pragma unroll
    for (int i = 0; i < 8; i++)
#pragma unroll
        for (int j = 0; j < 8; j++) acc[i][j] = 0.0f;

    int lr = t >> 2;
    int lc = (t & 3) * 4;

    for (int kc = 0; kc < 128; kc += 16) {
#pragma unroll
        for (int h = 0; h < 2; ++h) {
            int m = m0 + lr + h * 64;
            float4 v = make_float4(0.f, 0.f, 0.f, 0.f);
            if (m < M) {
                const float* arow = (m < splitM) ? (A0 + (size_t)m * 128)
                                                 : (A1 + (size_t)(m - splitM) * 128);
                v = *reinterpret_cast<const float4*>(arow + kc + lc);
            }
            As[lc + 0][lr + h * 64] = v.x;
            As[lc + 1][lr + h * 64] = v.y;
            As[lc + 2][lr + h * 64] = v.z;
            As[lc + 3][lr + h * 64] = v.w;
        }
#pragma unroll
        for (int h = 0; h < 2; ++h) {
            int n = n0 + lr + h * 64;
            float4 v = *reinterpret_cast<const float4*>(B + (size_t)n * 128 + kc + lc);
            Bs[lc + 0][lr + h * 64] = v.x;
            Bs[lc + 1][lr + h * 64] = v.y;
            Bs[lc + 2][lr + h * 64] = v.z;
            Bs[lc + 3][lr + h * 64] = v.w;
        }
        __syncthreads();

#pragma unroll
        for (int kk = 0; kk < 16; ++kk) {
            float af[8], bf[8];
            float4 a0v = *reinterpret_cast<const float4*>(&As[kk][ty * 8]);
            float4 a1v = *reinterpret_cast<const float4*>(&As[kk][ty * 8 + 4]);
            float4 b0v = *reinterpret_cast<const float4*>(&Bs[kk][tx * 8]);
            float4 b1v = *reinterpret_cast<const float4*>(&Bs[kk][tx * 8 + 4]);
            af[0]=a0v.x; af[1]=a0v.y; af[2]=a0v.z; af[3]=a0v.w;
            af[4]=a1v.x; af[5]=a1v.y; af[6]=a1v.z; af[7]=a1v.w;
            bf[0]=b0v.x; bf[1]=b0v.y; bf[2]=b0v.z; bf[3]=b0v.w;
            bf[4]=b1v.x; bf[5]=b1v.y; bf[6]=b1v.z; bf[7]=b1v.w;
#pragma unroll
            for (int i = 0; i < 8; i++)
#pragma unroll
                for (int j = 0; j < 8; j++)
                    acc[i][j] = fmaf(af[i], bf[j], acc[i][j]);
        }
        __syncthreads();
    }

    if (mode == 0) {
#pragma unroll
        for (int i = 0; i < 8; i++) {
            int m = m0 + ty * 8 + i;
            if (m >= M) continue;
            float* crow = C + (size_t)m * ldc + n0 + tx * 8;
            *reinterpret_cast<float4*>(crow)     = make_float4(acc[i][0], acc[i][1], acc[i][2], acc[i][3]);
            *reinterpret_cast<float4*>(crow + 4) = make_float4(acc[i][4], acc[i][5], acc[i][6], acc[i][7]);
        }
        return;
    }

    // ---- fused edge epilogue (mode 1, n0 == 0, row = edge id) ----
    float4 a2a = *reinterpret_cast<const float4*>(a2 + tx * 8);
    float4 a2b = *reinterpret_cast<const float4*>(a2 + tx * 8 + 4);

#pragma unroll
    for (int i = 0; i < 8; i++) {
        int m = m0 + ty * 8 + i;
        bool valid = (m < M);
        float s = 0.0f;
        int dst = 0;
        float mv[8];
        if (valid) {
            int src;
            edge_src_dst(edge, nhop, m, E1, E2, src, dst);
            const float* prow = g_PQ + (size_t)src * 256 + tx * 8;
            const float* qrow = g_PQ + (size_t)dst * 256 + 128 + tx * 8;
            float4 pa = *reinterpret_cast<const float4*>(prow);
            float4 pb = *reinterpret_cast<const float4*>(prow + 4);
            float4 qa = *reinterpret_cast<const float4*>(qrow);
            float4 qb = *reinterpret_cast<const float4*>(qrow + 4);
            mv[0] = lrelu(acc[i][0] + pa.x + qa.x);
            mv[1] = lrelu(acc[i][1] + pa.y + qa.y);
            mv[2] = lrelu(acc[i][2] + pa.z + qa.z);
            mv[3] = lrelu(acc[i][3] + pa.w + qa.w);
            mv[4] = lrelu(acc[i][4] + pb.x + qb.x);
            mv[5] = lrelu(acc[i][5] + pb.y + qb.y);
            mv[6] = lrelu(acc[i][6] + pb.z + qb.z);
            mv[7] = lrelu(acc[i][7] + pb.w + qb.w);
            float* crow = C + (size_t)m * 128 + tx * 8;
            *reinterpret_cast<float4*>(crow)     = make_float4(mv[0], mv[1], mv[2], mv[3]);
            *reinterpret_cast<float4*>(crow + 4) = make_float4(mv[4], mv[5], mv[6], mv[7]);
            s = mv[0]*a2a.x + mv[1]*a2a.y + mv[2]*a2a.z + mv[3]*a2a.w
              + mv[4]*a2b.x + mv[5]*a2b.y + mv[6]*a2b.z + mv[7]*a2b.w;
        }
        // 16-lane reduction (lanes with same ty share a row; xor stays in group)
#pragma unroll
        for (int off = 8; off > 0; off >>= 1)
            s += __shfl_xor_sync(0xffffffffu, s, off);
        if (valid && tx == 0) {
            float ee = expf(-lrelu(s));
            g_edge_e[m] = ee;
            atomicAdd(&g_arow[dst], ee);
        }
    }
}

// ---------------- rel_att + e_rowsum ----------------
__global__ void k_rel(const int* __restrict__ edge, const int* __restrict__ nhop,
                      int E1, int E2, int E)
{
    int e = blockIdx.x * blockDim.x + threadIdx.x;
    if (e >= E) return;
    int src, dst;
    edge_src_dst(edge, nhop, e, E1, E2, src, dst);
    float as = g_arow[dst];
    if (as == 0.0f) as = 1e-12f;
    float r = g_edge_e[e] / as;
    g_rel_att[e] = r;
    atomicAdd(&g_erow[src], r);
}

// ---------------- val + e_colsum ----------------
__global__ void k_val(const int* __restrict__ edge, const int* __restrict__ nhop,
                      const float* __restrict__ entity_rank, int E1, int E2, int E)
{
    int e = blockIdx.x * blockDim.x + threadIdx.x;
    if (e >= E) return;
    int src, dst;
    edge_src_dst(edge, nhop, e, E1, E2, src, dst);
    float es = g_erow[src];
    if (es == 0.0f) es = 1e-12f;
    float v = g_rel_att[e] * entity_rank[src] / es;
    atomicAdd(&g_ecol[dst], v);
}

// ---------------- new_rank ----------------
__global__ void k_rank(float* __restrict__ out, int N, int out_size) {
    int n = blockIdx.x * blockDim.x + threadIdx.x;
    if (n >= N) return;
    float nr = 0.15f + 0.85f * g_ecol[n];
    g_new_rank[n] = nr;
    if (out_size >= N * 128 + N) out[(size_t)N * 128 + n] = nr;
}

// ---------------- scatter with vector RED ----------------
__global__ __launch_bounds__(128) void k_scatter(
    const int* __restrict__ edge, const int* __restrict__ nhop,
    float* __restrict__ out, int E1, int E2, int E)
{
    int e = blockIdx.x * 4 + (threadIdx.x >> 5);
    if (e >= E) return;
    int lane = threadIdx.x & 31;
    int src, dst;
    edge_src_dst(edge, nhop, e, E1, E2, src, dst);
    float w = g_rel_att[e] * g_new_rank[src];
    float4 v = *reinterpret_cast<const float4*>(&g_edge_m[(size_t)e * 128 + lane * 4]);
    float* p = out + (size_t)dst * 128 + lane * 4;
    asm volatile("red.global.add.v4.f32 [%0], {%1, %2, %3, %4};"
                 :: "l"(p), "f"(w * v.x), "f"(w * v.y), "f"(w * v.z), "f"(w * v.w)
                 : "memory");
}

// ---------------- ELU ----------------
__global__ void k_elu(float* __restrict__ out, int total) {
    int i = blockIdx.x * blockDim.x + threadIdx.x;
    if (i >= total) return;
    float x = out[i];
    out[i] = (x > 0.0f) ? x : expm1f(x);
}

// ---------------- launch ----------------
extern "C" void kernel_launch(void* const* d_in, const int* in_sizes, int n_in,
                              void* d_out, int out_size) {
    const float* input       = (const float*)d_in[0];
    const int*   edge        = (const int*)d_in[1];
    const float* edge_embed  = (const float*)d_in[2];
    const int*   edge_nhop   = (const int*)d_in[3];
    const float* embed_nhop  = (const float*)d_in[4];
    const float* entity_rank = (const float*)d_in[5];
    const float* a           = (const float*)d_in[6];
    const float* a2          = (const float*)d_in[7];
    float* out = (float*)d_out;

    int N  = in_sizes[0] / 128;
    int E1 = in_sizes[1] / 2;
    int E2 = in_sizes[3] / 2;
    int E  = E1 + E2;

    k_init<<<(N * 128 + 255) / 256, 256>>>(out, N);
    k_prep<<<(256 * 128 + 255) / 256, 256>>>(a);

    // P|Q for all nodes
    dim3 g_pq((N + 127) / 128, 2);
    k_sgemm<<<g_pq, 256>>>(input, input, N, N, 0, nullptr, nullptr, nullptr, 0, 0);

    // R = emb @ A3^T fused with edge_m/edge_e/a_rowsum epilogue
    dim3 g_r((E + 127) / 128, 1);
    k_sgemm<<<g_r, 256>>>(edge_embed, embed_nhop, E1, E, 1, edge, edge_nhop, a2, E1, E2);

    k_rel<<<(E + 255) / 256, 256>>>(edge, edge_nhop, E1, E2, E);
    k_val<<<(E + 255) / 256, 256>>>(edge, edge_nhop, entity_rank, E1, E2, E);
    k_rank<<<(N + 255) / 256, 256>>>(out, N, out_size);
    k_scatter<<<(E + 3) / 4, 128>>>(edge, edge_nhop, out, E1, E2, E);
    k_elu<<<(N * 128 + 255) / 256, 256>>>(out, N * 128);
}

// round 8
// speedup vs baseline: 1.8147x; 1.1463x over previous
#include <cuda_runtime.h>
#include <cstdint>
#include <cstddef>

#define N_MAX 50000
#define E_MAX 500000

// ---------------- scratch ----------------
__device__ float g_PQ[(size_t)N_MAX * 256];
__device__ float g_edge_m[(size_t)E_MAX * 128];
__device__ float g_B1[256 * 128];
__device__ float g_B3[128 * 128];
__device__ float g_edge_e[E_MAX];
__device__ float g_rel_att[E_MAX];
__device__ float g_arow[N_MAX];
__device__ float g_erow[N_MAX];
__device__ float g_ecol[N_MAX];
__device__ float g_new_rank[N_MAX];

// ---------------- init ----------------
__global__ void k_init(float* __restrict__ out, int N) {
    int i = blockIdx.x * blockDim.x + threadIdx.x;
    int total = N * 128;
    if (i < total) out[i] = 0.0f;
    if (i < N) { g_arow[i] = 0.0f; g_erow[i] = 0.0f; g_ecol[i] = 0.0f; }
}

// ---------------- weight extraction ----------------
__global__ void k_prep(const float* __restrict__ a) {
    int i = blockIdx.x * blockDim.x + threadIdx.x;
    if (i < 256 * 128) {
        int o = i >> 7, k = i & 127;
        g_B1[i] = (o < 128) ? a[o * 384 + k] : a[(o - 128) * 384 + 128 + k];
    }
    if (i < 128 * 128) {
        int o = i >> 7, k = i & 127;
        g_B3[i] = a[o * 384 + 256 + k];
    }
}

__device__ __forceinline__ float lrelu(float x) { return (x > 0.0f) ? x : 0.2f * x; }

// edge indices are int32 (JAX downcasts int64 without x64 enabled)
__device__ __forceinline__ void edge_src_dst(
    const int* __restrict__ edge, const int* __restrict__ nhop,
    int e, int E1, int E2, int& src, int& dst)
{
    if (e < E1) { src = edge[e]; dst = edge[E1 + e]; }
    else        { int e2 = e - E1; src = nhop[e2]; dst = nhop[E2 + e2]; }
}

__device__ __forceinline__ float to_tf32(float x) {
    uint32_t u;
    asm("cvt.rna.tf32.f32 %0, %1;" : "=r"(u) : "f"(x));
    return __uint_as_float(u);
}

__device__ __forceinline__ void mma_tf32(float* c, const uint32_t* a, const uint32_t* b) {
    asm volatile(
        "mma.sync.aligned.m16n8k8.row.col.f32.tf32.tf32.f32 "
        "{%0,%1,%2,%3}, {%4,%5,%6,%7}, {%8,%9}, {%0,%1,%2,%3};"
        : "+f"(c[0]), "+f"(c[1]), "+f"(c[2]), "+f"(c[3])
        : "r"(a[0]), "r"(a[1]), "r"(a[2]), "r"(a[3]), "r"(b[0]), "r"(b[1]));
}

// ---------------- tf32 tensor-core GEMM: C[m][n] = sum_k A[m][k]*B[n][k], K=128 ----------------
// Block tile 128x128, 8 warps (4 M x 2 N), warp tile 32x64 (2x8 m16n8k8 atoms).
// mode 0: B=g_B1 (256 rows, via blockIdx.y), C=g_PQ ldc=256, plain store.
// mode 1: B=g_B3, fused edge epilogue.
__global__ __launch_bounds__(256, 2) void k_sgemm(
    const float* __restrict__ A0, const float* __restrict__ A1, int splitM,
    int M, int mode,
    const int* __restrict__ edge, const int* __restrict__ nhop,
    const float* __restrict__ a2, int E1, int E2)
{
    __shared__ float As[128][36];
    __shared__ float Bs[128][36];
    __shared__ float a2s[128];
    __shared__ float sdot[128];

    const float* __restrict__ B = (mode == 0) ? g_B1 : g_B3;

    const int t     = threadIdx.x;
    const int lane  = t & 31;
    const int wid   = t >> 5;
    const int warpM = wid >> 1;   // 0..3
    const int warpN = wid & 1;    // 0..1
    const int m0    = blockIdx.x * 128;
    const int n0    = blockIdx.y * 128;

    if (t < 128) { sdot[t] = 0.0f; if (mode == 1) a2s[t] = a2[t]; }

    float acc[2][8][4];
#pragma unroll
    for (int i = 0; i < 2; i++)
#pragma unroll
        for (int j = 0; j < 8; j++)
#pragma unroll
            for (int c = 0; c < 4; c++) acc[i][j][c] = 0.0f;

    const int srow = t >> 3;        // 0..31
    const int scol = (t & 7) * 4;   // 0,4,...,28

    for (int kc = 0; kc < 128; kc += 32) {
#pragma unroll
        for (int p = 0; p < 4; ++p) {
            int m = m0 + p * 32 + srow;
            float4 v = make_float4(0.f, 0.f, 0.f, 0.f);
            if (m < M) {
                const float* arow = (m < splitM) ? (A0 + (size_t)m * 128)
                                                 : (A1 + (size_t)(m - splitM) * 128);
                v = *reinterpret_cast<const float4*>(arow + kc + scol);
            }
            float* d = &As[p * 32 + srow][scol];
            d[0] = to_tf32(v.x); d[1] = to_tf32(v.y);
            d[2] = to_tf32(v.z); d[3] = to_tf32(v.w);
        }
#pragma unroll
        for (int p = 0; p < 4; ++p) {
            int n = n0 + p * 32 + srow;
            float4 v = *reinterpret_cast<const float4*>(B + (size_t)n * 128 + kc + scol);
            float* d = &Bs[p * 32 + srow][scol];
            d[0] = to_tf32(v.x); d[1] = to_tf32(v.y);
            d[2] = to_tf32(v.z); d[3] = to_tf32(v.w);
        }
        __syncthreads();

#pragma unroll
        for (int ks = 0; ks < 4; ++ks) {
            const int kb = ks * 8 + (lane & 3);
            uint32_t af[2][4];
            const int r0 = warpM * 32 + (lane >> 2);
#pragma unroll
            for (int i = 0; i < 2; i++) {
                int r = r0 + i * 16;
                af[i][0] = __float_as_uint(As[r][kb]);
                af[i][1] = __float_as_uint(As[r + 8][kb]);
                af[i][2] = __float_as_uint(As[r][kb + 4]);
                af[i][3] = __float_as_uint(As[r + 8][kb + 4]);
            }
            uint32_t bf[8][2];
            const int nb = warpN * 64 + (lane >> 2);
#pragma unroll
            for (int j = 0; j < 8; j++) {
                bf[j][0] = __float_as_uint(Bs[nb + j * 8][kb]);
                bf[j][1] = __float_as_uint(Bs[nb + j * 8][kb + 4]);
            }
#pragma unroll
            for (int i = 0; i < 2; i++)
#pragma unroll
                for (int j = 0; j < 8; j++)
                    mma_tf32(acc[i][j], af[i], bf[j]);
        }
        __syncthreads();
    }

    if (mode == 0) {
#pragma unroll
        for (int i = 0; i < 2; i++) {
            int m = m0 + warpM * 32 + i * 16 + (lane >> 2);
#pragma unroll
            for (int j = 0; j < 8; j++) {
                int col = n0 + warpN * 64 + j * 8 + 2 * (lane & 3);
                if (m < M)
                    *reinterpret_cast<float2*>(&g_PQ[(size_t)m * 256 + col]) =
                        make_float2(acc[i][j][0], acc[i][j][1]);
                if (m + 8 < M)
                    *reinterpret_cast<float2*>(&g_PQ[(size_t)(m + 8) * 256 + col]) =
                        make_float2(acc[i][j][2], acc[i][j][3]);
            }
        }
        return;
    }

    // ---- fused edge epilogue (mode 1, n0 == 0, row = edge id) ----
#pragma unroll
    for (int i = 0; i < 2; i++) {
#pragma unroll
        for (int half = 0; half < 2; half++) {
            int rl = warpM * 32 + i * 16 + (lane >> 2) + 8 * half;
            int m = m0 + rl;
            float s = 0.0f;
            if (m < M) {
                int src, dst;
                edge_src_dst(edge, nhop, m, E1, E2, src, dst);
                const float* pbase = g_PQ + (size_t)src * 256;
                const float* qbase = g_PQ + (size_t)dst * 256 + 128;
                float* crow = g_edge_m + (size_t)m * 128;
#pragma unroll
                for (int j = 0; j < 8; j++) {
                    int col = warpN * 64 + j * 8 + 2 * (lane & 3);
                    float c0 = acc[i][j][half * 2 + 0];
                    float c1 = acc[i][j][half * 2 + 1];
                    float2 pv = *reinterpret_cast<const float2*>(pbase + col);
                    float2 qv = *reinterpret_cast<const float2*>(qbase + col);
                    float v0 = lrelu(c0 + pv.x + qv.x);
                    float v1 = lrelu(c1 + pv.y + qv.y);
                    *reinterpret_cast<float2*>(crow + col) = make_float2(v0, v1);
                    s += v0 * a2s[col] + v1 * a2s[col + 1];
                }
            }
            s += __shfl_xor_sync(0xffffffffu, s, 1);
            s += __shfl_xor_sync(0xffffffffu, s, 2);
            if ((lane & 3) == 0 && m < M) atomicAdd(&sdot[rl], s);
        }
    }
    __syncthreads();
    if (t < 128) {
        int m = m0 + t;
        if (m < M) {
            int src, dst;
            edge_src_dst(edge, nhop, m, E1, E2, src, dst);
            float ee = expf(-lrelu(sdot[t]));
            g_edge_e[m] = ee;
            atomicAdd(&g_arow[dst], ee);
        }
    }
}

// ---------------- rel_att + e_rowsum ----------------
__global__ void k_rel(const int* __restrict__ edge, const int* __restrict__ nhop,
                      int E1, int E2, int E)
{
    int e = blockIdx.x * blockDim.x + threadIdx.x;
    if (e >= E) return;
    int src, dst;
    edge_src_dst(edge, nhop, e, E1, E2, src, dst);
    float as = g_arow[dst];
    if (as == 0.0f) as = 1e-12f;
    float r = g_edge_e[e] / as;
    g_rel_att[e] = r;
    atomicAdd(&g_erow[src], r);
}

// ---------------- val + e_colsum ----------------
__global__ void k_val(const int* __restrict__ edge, const int* __restrict__ nhop,
                      const float* __restrict__ entity_rank, int E1, int E2, int E)
{
    int e = blockIdx.x * blockDim.x + threadIdx.x;
    if (e >= E) return;
    int src, dst;
    edge_src_dst(edge, nhop, e, E1, E2, src, dst);
    float es = g_erow[src];
    if (es == 0.0f) es = 1e-12f;
    float v = g_rel_att[e] * entity_rank[src] / es;
    atomicAdd(&g_ecol[dst], v);
}

// ---------------- new_rank ----------------
__global__ void k_rank(float* __restrict__ out, int N, int out_size) {
    int n = blockIdx.x * blockDim.x + threadIdx.x;
    if (n >= N) return;
    float nr = 0.15f + 0.85f * g_ecol[n];
    g_new_rank[n] = nr;
    if (out_size >= N * 128 + N) out[(size_t)N * 128 + n] = nr;
}

// ---------------- scatter with vector RED ----------------
__global__ __launch_bounds__(128) void k_scatter(
    const int* __restrict__ edge, const int* __restrict__ nhop,
    float* __restrict__ out, int E1, int E2, int E)
{
    int e = blockIdx.x * 4 + (threadIdx.x >> 5);
    if (e >= E) return;
    int lane = threadIdx.x & 31;
    int src, dst;
    edge_src_dst(edge, nhop, e, E1, E2, src, dst);
    float w = g_rel_att[e] * g_new_rank[src];
    float4 v = *reinterpret_cast<const float4*>(&g_edge_m[(size_t)e * 128 + lane * 4]);
    float* p = out + (size_t)dst * 128 + lane * 4;
    asm volatile("red.global.add.v4.f32 [%0], {%1, %2, %3, %4};"
                 :: "l"(p), "f"(w * v.x), "f"(w * v.y), "f"(w * v.z), "f"(w * v.w)
                 : "memory");
}

// ---------------- ELU ----------------
__global__ void k_elu(float* __restrict__ out, int total) {
    int i = blockIdx.x * blockDim.x + threadIdx.x;
    if (i >= total) return;
    float x = out[i];
    out[i] = (x > 0.0f) ? x : expm1f(x);
}

// ---------------- launch ----------------
extern "C" void kernel_launch(void* const* d_in, const int* in_sizes, int n_in,
                              void* d_out, int out_size) {
    const float* input       = (const float*)d_in[0];
    const int*   edge        = (const int*)d_in[1];
    const float* edge_embed  = (const float*)d_in[2];
    const int*   edge_nhop   = (const int*)d_in[3];
    const float* embed_nhop  = (const float*)d_in[4];
    const float* entity_rank = (const float*)d_in[5];
    const float* a           = (const float*)d_in[6];
    const float* a2          = (const float*)d_in[7];
    float* out = (float*)d_out;

    int N  = in_sizes[0] / 128;
    int E1 = in_sizes[1] / 2;
    int E2 = in_sizes[3] / 2;
    int E  = E1 + E2;

    k_init<<<(N * 128 + 255) / 256, 256>>>(out, N);
    k_prep<<<(256 * 128 + 255) / 256, 256>>>(a);

    // P|Q for all nodes
    dim3 g_pq((N + 127) / 128, 2);
    k_sgemm<<<g_pq, 256>>>(input, input, N, N, 0, nullptr, nullptr, nullptr, 0, 0);

    // R = emb @ A3^T fused with edge_m/edge_e/a_rowsum epilogue
    dim3 g_r((E + 127) / 128, 1);
    k_sgemm<<<g_r, 256>>>(edge_embed, embed_nhop, E1, E, 1, edge, edge_nhop, a2, E1, E2);

    k_rel<<<(E + 255) / 256, 256>>>(edge, edge_nhop, E1, E2, E);
    k_val<<<(E + 255) / 256, 256>>>(edge, edge_nhop, entity_rank, E1, E2, E);
    k_rank<<<(N + 255) / 256, 256>>>(out, N, out_size);
    k_scatter<<<(E + 3) / 4, 128>>>(edge, edge_nhop, out, E1, E2, E);
    k_elu<<<(N * 128 + 255) / 256, 256>>>(out, N * 128);
}

// round 11
// speedup vs baseline: 2.5548x; 1.4078x over previous
#include <cuda_runtime.h>
#include <cstdint>
#include <cstddef>

#define N_MAX 50000
#define E_MAX 500000

// ---------------- scratch ----------------
__device__ float g_PQ[(size_t)N_MAX * 256];
__device__ float g_edge_m[(size_t)E_MAX * 128];
__device__ float g_B1[256 * 128];
__device__ float g_B3[128 * 128];
__device__ float g_edge_e[E_MAX];
__device__ float g_rel_att[E_MAX];
__device__ float g_arow[N_MAX];
__device__ float g_erow[N_MAX];
__device__ float g_ecol[N_MAX];
__device__ float g_new_rank[N_MAX];

// ---------------- init ----------------
__global__ void k_init(float* __restrict__ out, int N) {
    int i = blockIdx.x * blockDim.x + threadIdx.x;
    int total = N * 128;
    if (i < total) out[i] = 0.0f;
    if (i < N) { g_arow[i] = 0.0f; g_erow[i] = 0.0f; g_ecol[i] = 0.0f; }
}

// ---------------- weight extraction ----------------
__global__ void k_prep(const float* __restrict__ a) {
    int i = blockIdx.x * blockDim.x + threadIdx.x;
    if (i < 256 * 128) {
        int o = i >> 7, k = i & 127;
        g_B1[i] = (o < 128) ? a[o * 384 + k] : a[(o - 128) * 384 + 128 + k];
    }
    if (i < 128 * 128) {
        int o = i >> 7, k = i & 127;
        g_B3[i] = a[o * 384 + 256 + k];
    }
}

__device__ __forceinline__ float lrelu(float x) { return (x > 0.0f) ? x : 0.2f * x; }

// edge indices are int32 (JAX downcasts int64 without x64 enabled)
__device__ __forceinline__ void edge_src_dst(
    const int* __restrict__ edge, const int* __restrict__ nhop,
    int e, int E1, int E2, int& src, int& dst)
{
    if (e < E1) { src = edge[e]; dst = edge[E1 + e]; }
    else        { int e2 = e - E1; src = nhop[e2]; dst = nhop[E2 + e2]; }
}

__device__ __forceinline__ float to_tf32(float x) {
    uint32_t u;
    asm("cvt.rna.tf32.f32 %0, %1;" : "=r"(u) : "f"(x));
    return __uint_as_float(u);
}

__device__ __forceinline__ void mma_tf32(float* c, const uint32_t* a, const uint32_t* b) {
    asm volatile(
        "mma.sync.aligned.m16n8k8.row.col.f32.tf32.tf32.f32 "
        "{%0,%1,%2,%3}, {%4,%5,%6,%7}, {%8,%9}, {%0,%1,%2,%3};"
        : "+f"(c[0]), "+f"(c[1]), "+f"(c[2]), "+f"(c[3])
        : "r"(a[0]), "r"(a[1]), "r"(a[2]), "r"(a[3]), "r"(b[0]), "r"(b[1]));
}

// ---------------- tf32 tensor-core GEMM: C[m][n] = sum_k A[m][k]*B[n][k], K=128 ----------------
// Block tile 128x128, 8 warps (4 M x 2 N), warp tile 32x64 (2x8 m16n8k8 atoms).
// Fragment-permuted smem: A fragments read with LDS.128, B with LDS.64 (lane-linear).
// A is register-prefetched one K-chunk ahead (DRAM latency hidden under MMAs).
// mode 0: B=g_B1, C=g_PQ ldc=256, plain store.  mode 1: B=g_B3, fused edge epilogue.
__global__ __launch_bounds__(256, 2) void k_sgemm(
    const float* __restrict__ A0, const float* __restrict__ A1, int splitM,
    int M, int mode,
    const int* __restrict__ edge, const int* __restrict__ nhop,
    const float* __restrict__ a2, int E1, int E2)
{
    // A: 32 segments [(rb*2+i)*4+ks] of 33 float4 (lane-indexed, +1 pad)
    // B: 64 segments [(wN*8+j)*4+ks] of 33 float2
    __shared__ __align__(16) float As_f[32 * 132];
    __shared__ __align__(16) float Bs_f[64 * 66];
    __shared__ float a2s[128];
    __shared__ float sdot[128];

    const float* __restrict__ B = (mode == 0) ? g_B1 : g_B3;

    const int t     = threadIdx.x;
    const int lane  = t & 31;
    const int wid   = t >> 5;
    const int warpM = wid >> 1;   // 0..3
    const int warpN = wid & 1;    // 0..1
    const int m0    = blockIdx.x * 128;
    const int n0    = blockIdx.y * 128;

    if (t < 128) { sdot[t] = 0.0f; if (mode == 1) a2s[t] = a2[t]; }

    float acc[2][8][4];
#pragma unroll
    for (int i = 0; i < 2; i++)
#pragma unroll
        for (int j = 0; j < 8; j++)
#pragma unroll
            for (int c = 0; c < 4; c++) acc[i][j][c] = 0.0f;

    const int srow = t >> 3;        // 0..31 (row within 32-row block)
    const int scol = (t & 7) * 4;   // 0,4,...,28 (k within 32-k chunk)

    // staging decomposition (constant per thread)
    const int i_s   = srow >> 4;                       // 0..1
    const int lane0 = (srow & 7) << 2;                 // 0..28
    const int ks_s  = scol >> 3;                       // 0..3
    const int cA    = ((scol >> 2) & 1) * 2 + ((srow >> 3) & 1);
    const int cB    = (scol >> 2) & 1;

    // A prefetch registers (one K-chunk: 4 row-blocks x float4)
    float4 pa[4];
    auto loadA = [&](int kc) {
#pragma unroll
        for (int p = 0; p < 4; ++p) {
            int m = m0 + p * 32 + srow;
            float4 v = make_float4(0.f, 0.f, 0.f, 0.f);
            if (m < M) {
                const float* arow = (m < splitM) ? (A0 + (size_t)m * 128)
                                                 : (A1 + (size_t)(m - splitM) * 128);
                v = *reinterpret_cast<const float4*>(arow + kc + scol);
            }
            pa[p] = v;
        }
    };

    loadA(0);

    for (int kc = 0; kc < 128; kc += 32) {
        // ---- stage A (from prefetch regs) into permuted layout ----
#pragma unroll
        for (int p = 0; p < 4; ++p) {
            int segA = (p * 2 + i_s) * 4 + ks_s;
            float* ap = As_f + segA * 132 + lane0 * 4 + cA;
            ap[0]  = to_tf32(pa[p].x);
            ap[4]  = to_tf32(pa[p].y);
            ap[8]  = to_tf32(pa[p].z);
            ap[12] = to_tf32(pa[p].w);
        }
        // ---- stage B (L2-hot) into permuted layout ----
#pragma unroll
        for (int p = 0; p < 4; ++p) {
            int n = n0 + p * 32 + srow;
            float4 v = *reinterpret_cast<const float4*>(B + (size_t)n * 128 + kc + scol);
            int jB   = ((p << 2) + (srow >> 3)) & 7;
            int segB = ((p >> 1) * 8 + jB) * 4 + ks_s;
            float* bp = Bs_f + segB * 66 + lane0 * 2 + cB;
            bp[0] = to_tf32(v.x);
            bp[2] = to_tf32(v.y);
            bp[4] = to_tf32(v.z);
            bp[6] = to_tf32(v.w);
        }
        __syncthreads();

        if (kc < 96) loadA(kc + 32);   // prefetch next chunk; latency hides under MMAs

        // ---- MMA over this chunk ----
#pragma unroll
        for (int ks = 0; ks < 4; ++ks) {
            uint32_t af[2][4];
#pragma unroll
            for (int i = 0; i < 2; i++) {
                int seg = (warpM * 2 + i) * 4 + ks;
                float4 fa = reinterpret_cast<const float4*>(As_f + seg * 132)[lane];
                af[i][0] = __float_as_uint(fa.x);
                af[i][1] = __float_as_uint(fa.y);
                af[i][2] = __float_as_uint(fa.z);
                af[i][3] = __float_as_uint(fa.w);
            }
            uint32_t bf[8][2];
#pragma unroll
            for (int j = 0; j < 8; j++) {
                int seg = (warpN * 8 + j) * 4 + ks;
                float2 fb = reinterpret_cast<const float2*>(Bs_f + seg * 66)[lane];
                bf[j][0] = __float_as_uint(fb.x);
                bf[j][1] = __float_as_uint(fb.y);
            }
#pragma unroll
            for (int i = 0; i < 2; i++)
#pragma unroll
                for (int j = 0; j < 8; j++)
                    mma_tf32(acc[i][j], af[i], bf[j]);
        }
        __syncthreads();
    }

    if (mode == 0) {
#pragma unroll
        for (int i = 0; i < 2; i++) {
            int m = m0 + warpM * 32 + i * 16 + (lane >> 2);
#pragma unroll
            for (int j = 0; j < 8; j++) {
                int col = n0 + warpN * 64 + j * 8 + 2 * (lane & 3);
                if (m < M)
                    *reinterpret_cast<float2*>(&g_PQ[(size_t)m * 256 + col]) =
                        make_float2(acc[i][j][0], acc[i][j][1]);
                if (m + 8 < M)
                    *reinterpret_cast<float2*>(&g_PQ[(size_t)(m + 8) * 256 + col]) =
                        make_float2(acc[i][j][2], acc[i][j][3]);
            }
        }
        return;
    }

    // ---- fused edge epilogue (mode 1, n0 == 0, row = edge id) ----
#pragma unroll
    for (int i = 0; i < 2; i++) {
#pragma unroll
        for (int half = 0; half < 2; half++) {
            int rl = warpM * 32 + i * 16 + (lane >> 2) + 8 * half;
            int m = m0 + rl;
            float s = 0.0f;
            if (m < M) {
                int src, dst;
                edge_src_dst(edge, nhop, m, E1, E2, src, dst);
                const float* pbase = g_PQ + (size_t)src * 256;
                const float* qbase = g_PQ + (size_t)dst * 256 + 128;
                float* crow = g_edge_m + (size_t)m * 128;
#pragma unroll
                for (int j = 0; j < 8; j++) {
                    int col = warpN * 64 + j * 8 + 2 * (lane & 3);
                    float c0 = acc[i][j][half * 2 + 0];
                    float c1 = acc[i][j][half * 2 + 1];
                    float2 pv = *reinterpret_cast<const float2*>(pbase + col);
                    float2 qv = *reinterpret_cast<const float2*>(qbase + col);
                    float v0 = lrelu(c0 + pv.x + qv.x);
                    float v1 = lrelu(c1 + pv.y + qv.y);
                    *reinterpret_cast<float2*>(crow + col) = make_float2(v0, v1);
                    s += v0 * a2s[col] + v1 * a2s[col + 1];
                }
            }
            s += __shfl_xor_sync(0xffffffffu, s, 1);
            s += __shfl_xor_sync(0xffffffffu, s, 2);
            if ((lane & 3) == 0 && m < M) atomicAdd(&sdot[rl], s);
        }
    }
    __syncthreads();
    if (t < 128) {
        int m = m0 + t;
        if (m < M) {
            int src, dst;
            edge_src_dst(edge, nhop, m, E1, E2, src, dst);
            float ee = expf(-lrelu(sdot[t]));
            g_edge_e[m] = ee;
            atomicAdd(&g_arow[dst], ee);
        }
    }
}

// ---------------- rel_att + e_rowsum ----------------
__global__ void k_rel(const int* __restrict__ edge, const int* __restrict__ nhop,
                      int E1, int E2, int E)
{
    int e = blockIdx.x * blockDim.x + threadIdx.x;
    if (e >= E) return;
    int src, dst;
    edge_src_dst(edge, nhop, e, E1, E2, src, dst);
    float as = g_arow[dst];
    if (as == 0.0f) as = 1e-12f;
    float r = g_edge_e[e] / as;
    g_rel_att[e] = r;
    atomicAdd(&g_erow[src], r);
}

// ---------------- val + e_colsum ----------------
__global__ void k_val(const int* __restrict__ edge, const int* __restrict__ nhop,
                      const float* __restrict__ entity_rank, int E1, int E2, int E)
{
    int e = blockIdx.x * blockDim.x + threadIdx.x;
    if (e >= E) return;
    int src, dst;
    edge_src_dst(edge, nhop, e, E1, E2, src, dst);
    float es = g_erow[src];
    if (es == 0.0f) es = 1e-12f;
    float v = g_rel_att[e] * entity_rank[src] / es;
    atomicAdd(&g_ecol[dst], v);
}

// ---------------- new_rank ----------------
__global__ void k_rank(float* __restrict__ out, int N, int out_size) {
    int n = blockIdx.x * blockDim.x + threadIdx.x;
    if (n >= N) return;
    float nr = 0.15f + 0.85f * g_ecol[n];
    g_new_rank[n] = nr;
    if (out_size >= N * 128 + N) out[(size_t)N * 128 + n] = nr;
}

// ---------------- scatter with vector RED ----------------
__global__ __launch_bounds__(128) void k_scatter(
    const int* __restrict__ edge, const int* __restrict__ nhop,
    float* __restrict__ out, int E1, int E2, int E)
{
    int e = blockIdx.x * 4 + (threadIdx.x >> 5);
    if (e >= E) return;
    int lane = threadIdx.x & 31;
    int src, dst;
    edge_src_dst(edge, nhop, e, E1, E2, src, dst);
    float w = g_rel_att[e] * g_new_rank[src];
    float4 v = *reinterpret_cast<const float4*>(&g_edge_m[(size_t)e * 128 + lane * 4]);
    float* p = out + (size_t)dst * 128 + lane * 4;
    asm volatile("red.global.add.v4.f32 [%0], {%1, %2, %3, %4};"
                 :: "l"(p), "f"(w * v.x), "f"(w * v.y), "f"(w * v.z), "f"(w * v.w)
                 : "memory");
}

// ---------------- ELU ----------------
__global__ void k_elu(float* __restrict__ out, int total) {
    int i = blockIdx.x * blockDim.x + threadIdx.x;
    if (i >= total) return;
    float x = out[i];
    out[i] = (x > 0.0f) ? x : expm1f(x);
}

// ---------------- launch ----------------
extern "C" void kernel_launch(void* const* d_in, const int* in_sizes, int n_in,
                              void* d_out, int out_size) {
    const float* input       = (const float*)d_in[0];
    const int*   edge        = (const int*)d_in[1];
    const float* edge_embed  = (const float*)d_in[2];
    const int*   edge_nhop   = (const int*)d_in[3];
    const float* embed_nhop  = (const float*)d_in[4];
    const float* entity_rank = (const float*)d_in[5];
    const float* a           = (const float*)d_in[6];
    const float* a2          = (const float*)d_in[7];
    float* out = (float*)d_out;

    int N  = in_sizes[0] / 128;
    int E1 = in_sizes[1] / 2;
    int E2 = in_sizes[3] / 2;
    int E  = E1 + E2;

    k_init<<<(N * 128 + 255) / 256, 256>>>(out, N);
    k_prep<<<(256 * 128 + 255) / 256, 256>>>(a);

    // P|Q for all nodes
    dim3 g_pq((N + 127) / 128, 2);
    k_sgemm<<<g_pq, 256>>>(input, input, N, N, 0, nullptr, nullptr, nullptr, 0, 0);

    // R = emb @ A3^T fused with edge_m/edge_e/a_rowsum epilogue
    dim3 g_r((E + 127) / 128, 1);
    k_sgemm<<<g_r, 256>>>(edge_embed, embed_nhop, E1, E, 1, edge, edge_nhop, a2, E1, E2);

    k_rel<<<(E + 255) / 256, 256>>>(edge, edge_nhop, E1, E2, E);
    k_val<<<(E + 255) / 256, 256>>>(edge, edge_nhop, entity_rank, E1, E2, E);
    k_rank<<<(N + 255) / 256, 256>>>(out, N, out_size);
    k_scatter<<<(E + 3) / 4, 128>>>(edge, edge_nhop, out, E1, E2, E);
    k_elu<<<(N * 128 + 255) / 256, 256>>>(out, N * 128);
}